// round 2
// baseline (speedup 1.0000x reference)
#include <cuda_runtime.h>

#define NPTS 8192
#define D 200
#define TILE 128
#define KC 40
#define NCH (D / KC)      // 5
#define NT (NPTS / TILE)  // 64
#define TPB 256

// Scratch (allocation-free rules: __device__ globals)
__device__ float g_sq[NPTS];
__device__ int   g_lab[NPTS];
__device__ float g_part[NT * NT];
__device__ int   g_is64;

// ---------------------------------------------------------------------------
// Kernel 0: detect label dtype. If buffer is little-endian int64 with values
// <64, every odd int32 word is 0. If int32, odd words are real labels and are
// essentially never all zero (P ~ 64^-4096).
// ---------------------------------------------------------------------------
__global__ void detect_kernel(const int* __restrict__ lab32) {
    __shared__ int any;
    if (threadIdx.x == 0) any = 0;
    __syncthreads();
    int a = 0;
    for (int i = 2 * threadIdx.x + 1; i < NPTS; i += 2 * blockDim.x)
        a |= lab32[i];
    if (a) atomicOr(&any, 1);
    __syncthreads();
    if (threadIdx.x == 0) g_is64 = (any == 0) ? 1 : 0;
}

// ---------------------------------------------------------------------------
// Kernel 1: per-row squared norms + label narrowing. One warp per row.
// ---------------------------------------------------------------------------
__global__ void prep_kernel(const float* __restrict__ x,
                            const int* __restrict__ lab32) {
    int row  = blockIdx.x * (TPB / 32) + (threadIdx.x >> 5);
    int lane = threadIdx.x & 31;
    const float* xr = x + (size_t)row * D;
    float s = 0.f;
    for (int k = lane; k < D; k += 32) {
        float v = xr[k];
        s = fmaf(v, v, s);
    }
#pragma unroll
    for (int o = 16; o; o >>= 1) s += __shfl_xor_sync(0xffffffffu, s, o);
    if (lane == 0) {
        g_sq[row]  = s;
        // int64 layout: value is the low word at index 2*row; int32: index row.
        g_lab[row] = g_is64 ? lab32[2 * row] : lab32[row];
    }
}

// ---------------------------------------------------------------------------
// Kernel 2: 128x128 pair tiles, upper triangle only (symmetry -> weight 2),
// fused Gram + sqrt + sign + block reduction. FMA-bound by design.
// ---------------------------------------------------------------------------
__global__ void __launch_bounds__(TPB, 2)
pair_kernel(const float* __restrict__ x) {
    const int ti = blockIdx.y;
    const int tj = blockIdx.x;
    if (tj < ti) {  // lower triangle: write 0 so the final reduce is uniform
        if (threadIdx.x == 0) g_part[ti * NT + tj] = 0.f;
        return;
    }

    __shared__ float As[TILE][KC];       // i-rows, row-major (a-reads broadcast)
    __shared__ float Bs[TILE][KC + 1];   // j-rows, padded -> 2-way max conflict
    __shared__ float sqA[TILE], sqB[TILE];
    __shared__ int   lA[TILE], lB[TILE];
    __shared__ float red[TPB / 32];

    const int t  = threadIdx.x;
    const int tx = t & 15;
    const int ty = t >> 4;

    if (t < TILE) {
        sqA[t] = g_sq[ti * TILE + t];
        lA[t]  = g_lab[ti * TILE + t];
        sqB[t] = g_sq[tj * TILE + t];
        lB[t]  = g_lab[tj * TILE + t];
    }

    float acc[8][8];
#pragma unroll
    for (int r = 0; r < 8; r++)
#pragma unroll
        for (int c = 0; c < 8; c++) acc[r][c] = 0.f;

    const float* xa = x + (size_t)ti * TILE * D;
    const float* xb = x + (size_t)tj * TILE * D;

    for (int ch = 0; ch < NCH; ch++) {
        __syncthreads();  // previous chunk fully consumed (also covers sq/lab)
        for (int i = t; i < TILE * KC; i += TPB) {
            int row = i / KC;
            int k   = i - row * KC;
            int g   = row * D + ch * KC + k;
            As[row][k] = xa[g];
            Bs[row][k] = xb[g];
        }
        __syncthreads();

#pragma unroll 4
        for (int k = 0; k < KC; k++) {
            float a[8], b[8];
#pragma unroll
            for (int r = 0; r < 4; r++) {
                a[r]     = As[ty * 4 + r][k];
                a[r + 4] = As[64 + ty * 4 + r][k];
            }
#pragma unroll
            for (int c = 0; c < 4; c++) {
                b[c]     = Bs[tx * 4 + c][k];
                b[c + 4] = Bs[64 + tx * 4 + c][k];
            }
#pragma unroll
            for (int r = 0; r < 8; r++)
#pragma unroll
                for (int c = 0; c < 8; c++)
                    acc[r][c] = fmaf(a[r], b[c], acc[r][c]);
        }
    }

    // Epilogue: d2 -> dist -> signed sum (diag skipped)
    float lsum = 0.f;
#pragma unroll
    for (int r = 0; r < 8; r++) {
        int m = 4 * ty + (r & 3) + ((r >> 2) << 6);
        float si = sqA[m];
        int   li = lA[m];
#pragma unroll
        for (int c = 0; c < 8; c++) {
            int n = 4 * tx + (c & 3) + ((c >> 2) << 6);
            float d2   = si + sqB[n] - 2.f * acc[r][c];
            float dist = sqrtf(fmaxf(d2, 0.f));
            float s    = (li == lB[n]) ? dist : -dist;
            bool  diag = (ti == tj) && (m == n);
            if (!diag) lsum += s;
        }
    }
    if (ti != tj) lsum *= 2.f;  // mirrored tile via symmetry

    // Deterministic block reduction
#pragma unroll
    for (int o = 16; o; o >>= 1) lsum += __shfl_xor_sync(0xffffffffu, lsum, o);
    if ((t & 31) == 0) red[t >> 5] = lsum;
    __syncthreads();
    if (t == 0) {
        float s = 0.f;
#pragma unroll
        for (int w = 0; w < TPB / 32; w++) s += red[w];
        g_part[ti * NT + tj] = s;
    }
}

// ---------------------------------------------------------------------------
// Kernel 3: deterministic final reduction in double, divide by N.
// ---------------------------------------------------------------------------
__global__ void reduce_kernel(float* __restrict__ out) {
    __shared__ double red[TPB];
    int t = threadIdx.x;
    double s = 0.0;
    for (int i = t; i < NT * NT; i += TPB) s += (double)g_part[i];
    red[t] = s;
    __syncthreads();
    for (int o = TPB / 2; o; o >>= 1) {
        if (t < o) red[t] += red[t + o];
        __syncthreads();
    }
    if (t == 0) out[0] = (float)(red[0] / (double)NPTS);
}

// ---------------------------------------------------------------------------
extern "C" void kernel_launch(void* const* d_in, const int* in_sizes, int n_in,
                              void* d_out, int out_size) {
    const float* x     = (const float*)d_in[0];
    const int*   lab32 = (const int*)d_in[1];
    float*       out   = (float*)d_out;

    detect_kernel<<<1, TPB>>>(lab32);
    prep_kernel<<<NPTS / (TPB / 32), TPB>>>(x, lab32);
    dim3 grid(NT, NT);
    pair_kernel<<<grid, TPB>>>(x);
    reduce_kernel<<<1, TPB>>>(out);
}

// round 3
// speedup vs baseline: 1.0217x; 1.0217x over previous
#include <cuda_runtime.h>

#define NPTS 8192
#define D 200
#define TILE 128
#define KC 25
#define NCH (D / KC)      // 8
#define NT (NPTS / TILE)  // 64
#define TPB 256

// Scratch (allocation-free rules: __device__ globals)
__device__ float g_sq[NPTS];
__device__ int   g_lab[NPTS];
__device__ float g_part[NT * NT];
__device__ int   g_is64;

// Packed f32x2 FMA (Blackwell, PTX-only): d.lo += a.lo*b.lo; d.hi += a.hi*b.hi
#define FMA2(d, a, b) \
    asm("fma.rn.f32x2 %0, %1, %2, %0;" : "+l"(d) : "l"(a), "l"(b))

// ---------------------------------------------------------------------------
// Kernel 0: detect label dtype (int64 little-endian with values <64 has all
// odd int32 words zero; int32 labels essentially never do).
// ---------------------------------------------------------------------------
__global__ void detect_kernel(const int* __restrict__ lab32) {
    __shared__ int any;
    if (threadIdx.x == 0) any = 0;
    __syncthreads();
    int a = 0;
    for (int i = 2 * threadIdx.x + 1; i < NPTS; i += 2 * blockDim.x)
        a |= lab32[i];
    if (a) atomicOr(&any, 1);
    __syncthreads();
    if (threadIdx.x == 0) g_is64 = (any == 0) ? 1 : 0;
}

// ---------------------------------------------------------------------------
// Kernel 1: per-row squared norms + label narrowing. One warp per row.
// ---------------------------------------------------------------------------
__global__ void prep_kernel(const float* __restrict__ x,
                            const int* __restrict__ lab32) {
    int row  = blockIdx.x * (TPB / 32) + (threadIdx.x >> 5);
    int lane = threadIdx.x & 31;
    const float* xr = x + (size_t)row * D;
    float s = 0.f;
    for (int k = lane; k < D; k += 32) {
        float v = xr[k];
        s = fmaf(v, v, s);
    }
#pragma unroll
    for (int o = 16; o; o >>= 1) s += __shfl_xor_sync(0xffffffffu, s, o);
    if (lane == 0) {
        g_sq[row]  = s;
        g_lab[row] = g_is64 ? lab32[2 * row] : lab32[row];
    }
}

// ---------------------------------------------------------------------------
// Kernel 2: 128x128 pair tiles, upper triangle only, Gram via packed FFMA2.
//   A tile pre-splatted in smem as (a,a) 8-byte pairs -> ld.shared.v2.u64
//   B tile transposed [k][n]                           -> ld.shared.v4.b32
//   32 fma.rn.f32x2 per k-step (== 64 FMA) per thread.
// ---------------------------------------------------------------------------
__global__ void __launch_bounds__(TPB, 2)
pair_kernel(const float* __restrict__ x) {
    const int ti = blockIdx.y;
    const int tj = blockIdx.x;
    if (tj < ti) {
        if (threadIdx.x == 0) g_part[ti * NT + tj] = 0.f;
        return;
    }

    __shared__ __align__(16) unsigned long long As2[KC][TILE + 2]; // splatted
    __shared__ __align__(16) float              Bs [KC][TILE + 4]; // transposed
    __shared__ float sqA[TILE], sqB[TILE];
    __shared__ int   lA[TILE], lB[TILE];
    __shared__ float red[TPB / 32];

    const int t   = threadIdx.x;
    const int tx  = t & 15;
    const int ty  = t >> 4;
    const int ty4 = ty * 4;
    const int tx4 = tx * 4;

    if (t < TILE) {
        sqA[t] = g_sq[ti * TILE + t];
        lA[t]  = g_lab[ti * TILE + t];
        sqB[t] = g_sq[tj * TILE + t];
        lB[t]  = g_lab[tj * TILE + t];
    }

    unsigned long long acc2[8][4];
#pragma unroll
    for (int r = 0; r < 8; r++)
#pragma unroll
        for (int c = 0; c < 4; c++) acc2[r][c] = 0ull;

    const float* xa = x + (size_t)ti * TILE * D;
    const float* xb = x + (size_t)tj * TILE * D;

    for (int ch = 0; ch < NCH; ch++) {
        __syncthreads();  // previous chunk consumed (also covers sq/lab)
        for (int i = t; i < TILE * KC; i += TPB) {
            int row = i / KC;
            int k   = i - row * KC;
            int g   = row * D + ch * KC + k;
            unsigned int ab = __float_as_uint(xa[g]);
            As2[k][row] = ((unsigned long long)ab << 32) | ab;  // splat (a,a)
            Bs[k][row]  = xb[g];
        }
        __syncthreads();

#pragma unroll 5
        for (int k = 0; k < KC; k++) {
            unsigned long long a2[8], b2[4];
            // A splats: 4x LDS.128, each broadcast (2 addrs/warp)
            asm("ld.shared.v2.u64 {%0,%1}, [%2];"
                : "=l"(a2[0]), "=l"(a2[1]) : "r"((unsigned)__cvta_generic_to_shared(&As2[k][ty4])));
            asm("ld.shared.v2.u64 {%0,%1}, [%2];"
                : "=l"(a2[2]), "=l"(a2[3]) : "r"((unsigned)__cvta_generic_to_shared(&As2[k][ty4 + 2])));
            asm("ld.shared.v2.u64 {%0,%1}, [%2];"
                : "=l"(a2[4]), "=l"(a2[5]) : "r"((unsigned)__cvta_generic_to_shared(&As2[k][64 + ty4])));
            asm("ld.shared.v2.u64 {%0,%1}, [%2];"
                : "=l"(a2[6]), "=l"(a2[7]) : "r"((unsigned)__cvta_generic_to_shared(&As2[k][64 + ty4 + 2])));
            // B pairs: 2x LDS.128 deliver 8 adjacent columns as 4 f32x2
            asm("{ .reg .b32 w0,w1,w2,w3;\n"
                "  ld.shared.v4.b32 {w0,w1,w2,w3}, [%2];\n"
                "  mov.b64 %0, {w0,w1};\n"
                "  mov.b64 %1, {w2,w3}; }"
                : "=l"(b2[0]), "=l"(b2[1]) : "r"((unsigned)__cvta_generic_to_shared(&Bs[k][tx4])));
            asm("{ .reg .b32 w0,w1,w2,w3;\n"
                "  ld.shared.v4.b32 {w0,w1,w2,w3}, [%2];\n"
                "  mov.b64 %0, {w0,w1};\n"
                "  mov.b64 %1, {w2,w3}; }"
                : "=l"(b2[2]), "=l"(b2[3]) : "r"((unsigned)__cvta_generic_to_shared(&Bs[k][64 + tx4])));
#pragma unroll
            for (int r = 0; r < 8; r++)
#pragma unroll
                for (int c = 0; c < 4; c++)
                    FMA2(acc2[r][c], a2[r], b2[c]);
        }
    }

    // Epilogue: d2 -> dist -> signed sum (diag skipped), symmetry weight 2
    float lsum = 0.f;
#pragma unroll
    for (int r = 0; r < 8; r++) {
        int m = ty4 + (r & 3) + ((r >> 2) << 6);
        float si = sqA[m];
        int   li = lA[m];
#pragma unroll
        for (int c = 0; c < 4; c++) {
            int n0 = tx4 + ((c & 1) << 1) + ((c >> 1) << 6);
            unsigned long long v = acc2[r][c];
            float glo = __uint_as_float((unsigned int)(v & 0xffffffffull));
            float ghi = __uint_as_float((unsigned int)(v >> 32));
#pragma unroll
            for (int h = 0; h < 2; h++) {
                int   n = n0 + h;
                float g = h ? ghi : glo;
                float d2   = si + sqB[n] - 2.f * g;
                float dist = sqrtf(fmaxf(d2, 0.f));
                float s    = (li == lB[n]) ? dist : -dist;
                bool  diag = (ti == tj) && (m == n);
                if (!diag) lsum += s;
            }
        }
    }
    if (ti != tj) lsum *= 2.f;

#pragma unroll
    for (int o = 16; o; o >>= 1) lsum += __shfl_xor_sync(0xffffffffu, lsum, o);
    if ((t & 31) == 0) red[t >> 5] = lsum;
    __syncthreads();
    if (t == 0) {
        float s = 0.f;
#pragma unroll
        for (int w = 0; w < TPB / 32; w++) s += red[w];
        g_part[ti * NT + tj] = s;
    }
}

// ---------------------------------------------------------------------------
// Kernel 3: deterministic final reduction in double, divide by N.
// ---------------------------------------------------------------------------
__global__ void reduce_kernel(float* __restrict__ out) {
    __shared__ double red[TPB];
    int t = threadIdx.x;
    double s = 0.0;
    for (int i = t; i < NT * NT; i += TPB) s += (double)g_part[i];
    red[t] = s;
    __syncthreads();
    for (int o = TPB / 2; o; o >>= 1) {
        if (t < o) red[t] += red[t + o];
        __syncthreads();
    }
    if (t == 0) out[0] = (float)(red[0] / (double)NPTS);
}

// ---------------------------------------------------------------------------
extern "C" void kernel_launch(void* const* d_in, const int* in_sizes, int n_in,
                              void* d_out, int out_size) {
    const float* x     = (const float*)d_in[0];
    const int*   lab32 = (const int*)d_in[1];
    float*       out   = (float*)d_out;

    detect_kernel<<<1, TPB>>>(lab32);
    prep_kernel<<<NPTS / (TPB / 32), TPB>>>(x, lab32);
    dim3 grid(NT, NT);
    pair_kernel<<<grid, TPB>>>(x);
    reduce_kernel<<<1, TPB>>>(out);
}

// round 5
// speedup vs baseline: 3.6010x; 3.5243x over previous
#include <cuda_runtime.h>
#include <cuda_bf16.h>
#include <cstdint>

#define NPTS 8192
#define D 200
#define K_PAD 256
#define ROW_BYTES (K_PAD * 2)      // 512
#define TM 128
#define TN 128
#define KC 64                      // bf16 per chunk (128 bytes/row)
#define NCH (K_PAD / KC)           // 4
#define NT (NPTS / TM)             // 64
#define NTILES (NT * NT)
#define TPB 256

// ---------------- device scratch (no allocations allowed) ----------------
__device__ __align__(16) unsigned char g_xb[(size_t)NPTS * ROW_BYTES]; // 4 MB bf16
__device__ float g_sq[NPTS];
__device__ int   g_lab[NPTS];
__device__ float g_part[NTILES];
__device__ int   g_is64;
__device__ unsigned int g_cnt;

// ---------------------------------------------------------------------------
// Kernel 0: label dtype detect + counter reset.
// ---------------------------------------------------------------------------
__global__ void detect_kernel(const int* __restrict__ lab32) {
    __shared__ int any;
    if (threadIdx.x == 0) { any = 0; g_cnt = 0; }
    __syncthreads();
    int a = 0;
    for (int i = 2 * threadIdx.x + 1; i < NPTS; i += 2 * blockDim.x) a |= lab32[i];
    if (a) atomicOr(&any, 1);
    __syncthreads();
    if (threadIdx.x == 0) g_is64 = (any == 0) ? 1 : 0;
}

// ---------------------------------------------------------------------------
// Kernel 1: x -> bf16 (zero-padded to K_PAD), sq from the SAME bf16 values,
// label narrowing. One warp per row, one 16B store per lane.
// ---------------------------------------------------------------------------
__global__ void prep_kernel(const float* __restrict__ x,
                            const int* __restrict__ lab32) {
    int row  = blockIdx.x * (TPB / 32) + (threadIdx.x >> 5);
    int lane = threadIdx.x & 31;
    int k0   = lane * 8;
    const float* xr = x + (size_t)row * D;
    float s = 0.f;
    uint32_t w[4];
#pragma unroll
    for (int p = 0; p < 4; p++) {
        int ka = k0 + 2 * p, kb = ka + 1;
        float f0 = (ka < D) ? xr[ka] : 0.f;
        float f1 = (kb < D) ? xr[kb] : 0.f;
        __nv_bfloat16 b0 = __float2bfloat16(f0);
        __nv_bfloat16 b1 = __float2bfloat16(f1);
        float g0 = __bfloat162float(b0), g1 = __bfloat162float(b1);
        s = fmaf(g0, g0, s);
        s = fmaf(g1, g1, s);
        w[p] = (uint32_t)__bfloat16_as_ushort(b0) |
               ((uint32_t)__bfloat16_as_ushort(b1) << 16);
    }
    *(uint4*)(g_xb + (size_t)row * ROW_BYTES + k0 * 2) = make_uint4(w[0], w[1], w[2], w[3]);
#pragma unroll
    for (int o = 16; o; o >>= 1) s += __shfl_xor_sync(0xffffffffu, s, o);
    if (lane == 0) {
        g_sq[row]  = s;
        g_lab[row] = g_is64 ? lab32[2 * row] : lab32[row];
    }
}

// ---------------------------------------------------------------------------
// Kernel 2: 128x128 Gram tiles via mma.sync m16n8k16 bf16 (sm_80 PTX path).
// 8 warps, warp tile 32(m) x 64(n). XOR-swizzled smem, conflict-free ldmatrix.
// Strict-upper (n>m) predicate, fused last-CTA final reduction.
// ---------------------------------------------------------------------------
__global__ void __launch_bounds__(TPB, 2)
pair_kernel(float* __restrict__ out) {
    __shared__ __align__(16) unsigned char sA[TM * 128];  // 16 KB, swizzled
    __shared__ __align__(16) unsigned char sB[TN * 128];  // 16 KB, swizzled
    __shared__ float sqA[TM], sqB[TN];
    __shared__ int   lA[TM], lB[TN];
    __shared__ float red[TPB / 32];
    __shared__ int    s_last;
    __shared__ double dred[TPB];

    const int t    = threadIdx.x;
    const int wid  = t >> 5;
    const int lane = t & 31;
    const int ti   = blockIdx.y;
    const int tj   = blockIdx.x;
    const int tile_id = ti * NT + tj;

    if (tj >= ti) {
        const int warp_m = wid >> 1;   // 0..3  -> 32 rows each
        const int warp_n = wid & 1;    // 0..1  -> 64 cols each

        const uint32_t sA0 = (uint32_t)__cvta_generic_to_shared(sA);
        const uint32_t sB0 = (uint32_t)__cvta_generic_to_shared(sB);

        // Per-lane ldmatrix row constants
        uint32_t arow[2], abase[2], arx[2];
#pragma unroll
        for (int f = 0; f < 2; f++) {
            arow[f]  = warp_m * 32 + f * 16 + (lane & 15);
            abase[f] = sA0 + arow[f] * 128;
            arx[f]   = arow[f] & 7;
        }
        const uint32_t akg = (lane >> 4);          // +0/+1 k-group
        uint32_t brow[4], bbase[4], brx[4];
#pragma unroll
        for (int h = 0; h < 4; h++) {
            brow[h]  = warp_n * 64 + h * 16 + (lane & 7) + ((lane >> 4) << 3);
            bbase[h] = sB0 + brow[h] * 128;
            brx[h]   = brow[h] & 7;
        }
        const uint32_t bkg = (lane >> 3) & 1;

        if (t < TM) { sqA[t] = g_sq[ti * TM + t]; lA[t] = g_lab[ti * TM + t]; }
        if (t < TN) { sqB[t] = g_sq[tj * TN + t]; lB[t] = g_lab[tj * TN + t]; }

        float acc[2][8][4];
#pragma unroll
        for (int f = 0; f < 2; f++)
#pragma unroll
            for (int j = 0; j < 8; j++)
#pragma unroll
                for (int e = 0; e < 4; e++) acc[f][j][e] = 0.f;

        const unsigned char* gA = g_xb + (size_t)(ti * TM) * ROW_BYTES;
        const unsigned char* gB = g_xb + (size_t)(tj * TN) * ROW_BYTES;

        for (int ch = 0; ch < NCH; ch++) {
            __syncthreads();
#pragma unroll
            for (int p = 0; p < 4; p++) {
                int G = t + TPB * p;       // 0..1023
                int row = G >> 3;
                int g   = G & 7;
                uint32_t soff = row * 128 + ((g ^ (row & 7)) << 4);
                size_t   goff = (size_t)row * ROW_BYTES + ch * 128 + g * 16;
                *(uint4*)(sA + soff) = *(const uint4*)(gA + goff);
                *(uint4*)(sB + soff) = *(const uint4*)(gB + goff);
            }
            __syncthreads();

#pragma unroll
            for (int ks = 0; ks < KC / 16; ks++) {
                uint32_t a[2][4], b[8][2];
#pragma unroll
                for (int f = 0; f < 2; f++) {
                    uint32_t kg = ks * 2 + akg;
                    uint32_t ad = abase[f] + ((kg ^ arx[f]) << 4);
                    asm volatile("ldmatrix.sync.aligned.m8n8.x4.shared.b16 {%0,%1,%2,%3}, [%4];"
                        : "=r"(a[f][0]), "=r"(a[f][1]), "=r"(a[f][2]), "=r"(a[f][3]) : "r"(ad));
                }
#pragma unroll
                for (int h = 0; h < 4; h++) {
                    uint32_t kg = ks * 2 + bkg;
                    uint32_t bd = bbase[h] + ((kg ^ brx[h]) << 4);
                    asm volatile("ldmatrix.sync.aligned.m8n8.x4.shared.b16 {%0,%1,%2,%3}, [%4];"
                        : "=r"(b[2 * h][0]), "=r"(b[2 * h][1]),
                          "=r"(b[2 * h + 1][0]), "=r"(b[2 * h + 1][1]) : "r"(bd));
                }
#pragma unroll
                for (int f = 0; f < 2; f++)
#pragma unroll
                    for (int j = 0; j < 8; j++)
                        asm volatile(
                            "mma.sync.aligned.m16n8k16.row.col.f32.bf16.bf16.f32 "
                            "{%0,%1,%2,%3}, {%4,%5,%6,%7}, {%8,%9}, {%0,%1,%2,%3};"
                            : "+f"(acc[f][j][0]), "+f"(acc[f][j][1]),
                              "+f"(acc[f][j][2]), "+f"(acc[f][j][3])
                            : "r"(a[f][0]), "r"(a[f][1]), "r"(a[f][2]), "r"(a[f][3]),
                              "r"(b[j][0]), "r"(b[j][1]));
            }
        }

        // Epilogue: d2 -> dist -> signed, strict upper (n > m) predicate.
        float lsum = 0.f;
        const int qrow = lane >> 2;         // 0..7
        const int qcol = (lane & 3) * 2;    // 0,2,4,6
#pragma unroll
        for (int f = 0; f < 2; f++) {
            int m0 = warp_m * 32 + f * 16 + qrow;
#pragma unroll
            for (int j = 0; j < 8; j++) {
                int n0 = warp_n * 64 + j * 8 + qcol;
#pragma unroll
                for (int e = 0; e < 4; e++) {
                    int m_loc = m0 + ((e >> 1) << 3);
                    int n_loc = n0 + (e & 1);
                    int gm = ti * TM + m_loc;
                    int gn = tj * TN + n_loc;
                    float d2   = sqA[m_loc] + sqB[n_loc] - 2.f * acc[f][j][e];
                    float dist = sqrtf(fmaxf(d2, 0.f));
                    float sgn  = (lA[m_loc] == lB[n_loc]) ? dist : -dist;
                    if (gn > gm) lsum += sgn;
                }
            }
        }
#pragma unroll
        for (int o = 16; o; o >>= 1) lsum += __shfl_xor_sync(0xffffffffu, lsum, o);
        if (lane == 0) red[wid] = lsum;
        __syncthreads();
        if (t == 0) {
            float s = 0.f;
#pragma unroll
            for (int w = 0; w < TPB / 32; w++) s += red[w];
            g_part[tile_id] = s;
        }
    } else {
        if (t == 0) g_part[tile_id] = 0.f;
    }

    // ---- last-CTA-done fused final reduction (deterministic order) ----
    __threadfence();
    if (t == 0) {
        unsigned old = atomicAdd(&g_cnt, 1u);
        s_last = (old == NTILES - 1) ? 1 : 0;
    }
    __syncthreads();
    if (s_last) {
        __threadfence();
        double acc = 0.0;
        for (int i = t; i < NTILES; i += TPB) acc += (double)g_part[i];
        dred[t] = acc;
        __syncthreads();
        for (int o = TPB / 2; o; o >>= 1) {
            if (t < o) dred[t] += dred[t + o];
            __syncthreads();
        }
        if (t == 0) out[0] = (float)(2.0 * dred[0] / (double)NPTS);
    }
}

// ---------------------------------------------------------------------------
extern "C" void kernel_launch(void* const* d_in, const int* in_sizes, int n_in,
                              void* d_out, int out_size) {
    const float* x     = (const float*)d_in[0];
    const int*   lab32 = (const int*)d_in[1];
    float*       outp  = (float*)d_out;

    detect_kernel<<<1, TPB>>>(lab32);
    prep_kernel<<<NPTS / (TPB / 32), TPB>>>(x, lab32);
    dim3 grid(NT, NT);
    pair_kernel<<<grid, TPB>>>(outp);
}

// round 6
// speedup vs baseline: 4.9075x; 1.3628x over previous
#include <cuda_runtime.h>
#include <cuda_bf16.h>
#include <cstdint>

#define NPTS 8192
#define D 200
#define ROW_BYTES 512              // bf16 rows zero-padded to 256 k
#define TM 128
#define NT (NPTS / TM)             // 64
#define NTRI (NT * (NT + 1) / 2)   // 2080 upper-triangle tiles
#define TPB 256
#define TILE_BYTES (TM * 128)      // 16 KB per operand buffer
#define SMEM_DYN (4 * TILE_BYTES)  // A0 A1 B0 B1

// ---------------- device scratch (no allocations allowed) ----------------
__device__ __align__(16) unsigned char g_xb[(size_t)NPTS * ROW_BYTES]; // 4 MB bf16
__device__ float g_sq[NPTS];
__device__ int   g_lab[NPTS];
__device__ float g_part[NTRI];
__device__ int   g_is64;
__device__ unsigned int g_cnt;

// ---------------- cp.async helpers (sm_80 PTX, ok under compute_103) -----
#define CP16(d, s) \
    asm volatile("cp.async.cg.shared.global [%0], [%1], 16;" :: "r"(d), "l"(s) : "memory")
#define CPC()  asm volatile("cp.async.commit_group;" ::: "memory")
#define CPW1() asm volatile("cp.async.wait_group 1;" ::: "memory")
#define CPW0() asm volatile("cp.async.wait_group 0;" ::: "memory")

// ---------------------------------------------------------------------------
// Kernel 0: label dtype detect + counter reset (safe bounds: odd idx < 8192).
// ---------------------------------------------------------------------------
__global__ void detect_kernel(const int* __restrict__ lab32) {
    __shared__ int any;
    if (threadIdx.x == 0) { any = 0; g_cnt = 0; }
    __syncthreads();
    int a = 0;
    for (int i = 2 * threadIdx.x + 1; i < NPTS; i += 2 * blockDim.x) a |= lab32[i];
    if (a) atomicOr(&any, 1);
    __syncthreads();
    if (threadIdx.x == 0) g_is64 = (any == 0) ? 1 : 0;
}

// ---------------------------------------------------------------------------
// Kernel 1: x -> bf16 (zero-padded), sq from the SAME bf16 values, labels.
// ---------------------------------------------------------------------------
__global__ void prep_kernel(const float* __restrict__ x,
                            const int* __restrict__ lab32) {
    int row  = blockIdx.x * (TPB / 32) + (threadIdx.x >> 5);
    int lane = threadIdx.x & 31;
    int k0   = lane * 8;
    const float* xr = x + (size_t)row * D;
    float s = 0.f;
    uint32_t w[4];
#pragma unroll
    for (int p = 0; p < 4; p++) {
        int ka = k0 + 2 * p, kb = ka + 1;
        float f0 = (ka < D) ? xr[ka] : 0.f;
        float f1 = (kb < D) ? xr[kb] : 0.f;
        __nv_bfloat16 b0 = __float2bfloat16(f0);
        __nv_bfloat16 b1 = __float2bfloat16(f1);
        float g0 = __bfloat162float(b0), g1 = __bfloat162float(b1);
        s = fmaf(g0, g0, s);
        s = fmaf(g1, g1, s);
        w[p] = (uint32_t)__bfloat16_as_ushort(b0) |
               ((uint32_t)__bfloat16_as_ushort(b1) << 16);
    }
    *(uint4*)(g_xb + (size_t)row * ROW_BYTES + k0 * 2) = make_uint4(w[0], w[1], w[2], w[3]);
#pragma unroll
    for (int o = 16; o; o >>= 1) s += __shfl_xor_sync(0xffffffffu, s, o);
    if (lane == 0) {
        g_sq[row]  = s;
        g_lab[row] = g_is64 ? lab32[2 * row] : lab32[row];
    }
}

// ---------------------------------------------------------------------------
// Chunk prefetch via cp.async (one commit group = A+B of one chunk).
// ---------------------------------------------------------------------------
__device__ __forceinline__ void prefetch(uint32_t dynA, int buf,
                                         const unsigned char* gA,
                                         const unsigned char* gB, int ch, int t) {
    uint32_t bofs = buf ? TILE_BYTES : 0u;
#pragma unroll
    for (int p = 0; p < 4; p++) {
        int G = t + TPB * p;            // 0..1023
        int row = G >> 3, g = G & 7;
        uint32_t soff = bofs + row * 128 + ((g ^ (row & 7)) << 4);
        size_t   goff = (size_t)row * ROW_BYTES + (size_t)ch * 128 + (size_t)g * 16;
        CP16(dynA + soff, gA + goff);
        CP16(dynA + 2 * TILE_BYTES + soff, gB + goff);
    }
    CPC();
}

// ---------------------------------------------------------------------------
// Kernel 2: triangular grid of 128x128 Gram tiles, mma.sync bf16,
// cp.async double buffer, 13 k-steps (K=208 covers D=200).
// ---------------------------------------------------------------------------
__global__ void __launch_bounds__(TPB, 2)
pair_kernel(float* __restrict__ out) {
    extern __shared__ __align__(128) unsigned char dyn[];
    __shared__ float sqA[TM], sqB[TM];
    __shared__ int   lA[TM], lB[TM];
    __shared__ float red[TPB / 32];
    __shared__ int    s_last;
    __shared__ double dred[TPB];

    const int t    = threadIdx.x;
    const int wid  = t >> 5;
    const int lane = t & 31;

    // linearized upper-triangle map: blockIdx.x -> (ti, tj), ti <= tj
    int bl = blockIdx.x, ti = 0;
    while (bl >= NT - ti) { bl -= NT - ti; ti++; }
    const int tj = ti + bl;

    const uint32_t dynA = (uint32_t)__cvta_generic_to_shared(dyn);
    const unsigned char* gA = g_xb + (size_t)(ti * TM) * ROW_BYTES;
    const unsigned char* gB = g_xb + (size_t)(tj * TM) * ROW_BYTES;

    prefetch(dynA, 0, gA, gB, 0, t);
    prefetch(dynA, 1, gA, gB, 1, t);

    if (t < TM) { sqA[t] = g_sq[ti * TM + t]; lA[t] = g_lab[ti * TM + t]; }
    else { int u = t - TM; sqB[u] = g_sq[tj * TM + u]; lB[u] = g_lab[tj * TM + u]; }

    const int warp_m = wid >> 1;   // 0..3 -> 32 rows
    const int warp_n = wid & 1;    // 0..1 -> 64 cols

    uint32_t abase[2], arx[2];
#pragma unroll
    for (int f = 0; f < 2; f++) {
        uint32_t arow = warp_m * 32 + f * 16 + (lane & 15);
        abase[f] = dynA + arow * 128;
        arx[f]   = arow & 7;
    }
    const uint32_t akg = lane >> 4;
    uint32_t bbase[4], brx[4];
#pragma unroll
    for (int h = 0; h < 4; h++) {
        uint32_t brow = warp_n * 64 + h * 16 + (lane & 7) + ((lane >> 4) << 3);
        bbase[h] = dynA + 2 * TILE_BYTES + brow * 128;
        brx[h]   = brow & 7;
    }
    const uint32_t bkg = (lane >> 3) & 1;

    float acc[2][8][4];
#pragma unroll
    for (int f = 0; f < 2; f++)
#pragma unroll
        for (int j = 0; j < 8; j++)
#pragma unroll
            for (int e = 0; e < 4; e++) acc[f][j][e] = 0.f;

#define KSTEP(ksv) do {                                                          \
    uint32_t a_[2][4], b_[8][2];                                                 \
    _Pragma("unroll")                                                            \
    for (int f = 0; f < 2; f++) {                                                \
        uint32_t kg = (uint32_t)(ksv) * 2 + akg;                                 \
        uint32_t ad = abase[f] + bofs + ((kg ^ arx[f]) << 4);                    \
        asm volatile("ldmatrix.sync.aligned.m8n8.x4.shared.b16 {%0,%1,%2,%3}, [%4];" \
            : "=r"(a_[f][0]), "=r"(a_[f][1]), "=r"(a_[f][2]), "=r"(a_[f][3]) : "r"(ad)); \
    }                                                                            \
    _Pragma("unroll")                                                            \
    for (int h = 0; h < 4; h++) {                                                \
        uint32_t kg = (uint32_t)(ksv) * 2 + bkg;                                 \
        uint32_t bd = bbase[h] + bofs + ((kg ^ brx[h]) << 4);                    \
        asm volatile("ldmatrix.sync.aligned.m8n8.x4.shared.b16 {%0,%1,%2,%3}, [%4];" \
            : "=r"(b_[2 * h][0]), "=r"(b_[2 * h][1]),                            \
              "=r"(b_[2 * h + 1][0]), "=r"(b_[2 * h + 1][1]) : "r"(bd));         \
    }                                                                            \
    _Pragma("unroll")                                                            \
    for (int f = 0; f < 2; f++)                                                  \
        _Pragma("unroll")                                                        \
        for (int j = 0; j < 8; j++)                                              \
            asm volatile(                                                        \
                "mma.sync.aligned.m16n8k16.row.col.f32.bf16.bf16.f32 "           \
                "{%0,%1,%2,%3}, {%4,%5,%6,%7}, {%8,%9}, {%0,%1,%2,%3};"          \
                : "+f"(acc[f][j][0]), "+f"(acc[f][j][1]),                        \
                  "+f"(acc[f][j][2]), "+f"(acc[f][j][3])                         \
                : "r"(a_[f][0]), "r"(a_[f][1]), "r"(a_[f][2]), "r"(a_[f][3]),    \
                  "r"(b_[j][0]), "r"(b_[j][1]));                                 \
} while (0)

#pragma unroll
    for (int ch = 0; ch < 4; ch++) {
        if (ch < 3) CPW1(); else CPW0();
        __syncthreads();
        const uint32_t bofs = (ch & 1) ? TILE_BYTES : 0u;
        KSTEP(0);
        if (ch < 3) { KSTEP(1); KSTEP(2); KSTEP(3); }  // 13 k-steps total
        __syncthreads();
        if (ch < 2) prefetch(dynA, ch & 1, gA, gB, ch + 2, t);
    }
#undef KSTEP

    // Epilogue: d2 -> dist -> signed, strict upper (n > m) predicate.
    float lsum = 0.f;
    const int qrow = lane >> 2;
    const int qcol = (lane & 3) * 2;
#pragma unroll
    for (int f = 0; f < 2; f++) {
        int m0 = warp_m * 32 + f * 16 + qrow;
#pragma unroll
        for (int j = 0; j < 8; j++) {
            int n0 = warp_n * 64 + j * 8 + qcol;
#pragma unroll
            for (int e = 0; e < 4; e++) {
                int m_loc = m0 + ((e >> 1) << 3);
                int n_loc = n0 + (e & 1);
                int gm = ti * TM + m_loc;
                int gn = tj * TM + n_loc;
                float d2   = sqA[m_loc] + sqB[n_loc] - 2.f * acc[f][j][e];
                float dist = sqrtf(fmaxf(d2, 0.f));
                float sgn  = (lA[m_loc] == lB[n_loc]) ? dist : -dist;
                if (gn > gm) lsum += sgn;
            }
        }
    }
#pragma unroll
    for (int o = 16; o; o >>= 1) lsum += __shfl_xor_sync(0xffffffffu, lsum, o);
    if (lane == 0) red[wid] = lsum;
    __syncthreads();
    if (t == 0) {
        float s = 0.f;
#pragma unroll
        for (int w = 0; w < TPB / 32; w++) s += red[w];
        g_part[blockIdx.x] = s;
    }

    // ---- last-CTA-done fused final reduction (deterministic order) ----
    __threadfence();
    if (t == 0) {
        unsigned old = atomicAdd(&g_cnt, 1u);
        s_last = (old == NTRI - 1) ? 1 : 0;
    }
    __syncthreads();
    if (s_last) {
        __threadfence();
        double acc2 = 0.0;
        for (int i = t; i < NTRI; i += TPB) acc2 += (double)g_part[i];
        dred[t] = acc2;
        __syncthreads();
        for (int o = TPB / 2; o; o >>= 1) {
            if (t < o) dred[t] += dred[t + o];
            __syncthreads();
        }
        if (t == 0) out[0] = (float)(2.0 * dred[0] / (double)NPTS);
    }
}

// ---------------------------------------------------------------------------
extern "C" void kernel_launch(void* const* d_in, const int* in_sizes, int n_in,
                              void* d_out, int out_size) {
    const float* x     = (const float*)d_in[0];
    const int*   lab32 = (const int*)d_in[1];
    float*       outp  = (float*)d_out;

    cudaFuncSetAttribute(pair_kernel, cudaFuncAttributeMaxDynamicSharedMemorySize,
                         SMEM_DYN);

    detect_kernel<<<1, TPB>>>(lab32);
    prep_kernel<<<NPTS / (TPB / 32), TPB>>>(x, lab32);
    pair_kernel<<<NTRI, TPB, SMEM_DYN>>>(outp);
}